// round 10
// baseline (speedup 1.0000x reference)
#include <cuda_runtime.h>
#include <math.h>

#define B_  2
#define T_  2048
#define D_  2048
#define H_  16
#define KV_ 4
#define HD_ 128

// Scratch (allocation-free rule: __device__ globals)
__device__ float g_q[(size_t)B_ * T_ * H_  * HD_];   // 32 MB
__device__ float g_k[(size_t)B_ * T_ * KV_ * HD_];   //  8 MB
__device__ float g_v[(size_t)B_ * T_ * KV_ * HD_];   //  8 MB
__device__ float g_o[(size_t)B_ * T_ * H_  * HD_];   // 32 MB

__device__ __forceinline__ unsigned f2tf(float x) {
    unsigned r;
    asm("cvt.rna.tf32.f32 %0, %1;" : "=r"(r) : "f"(x));
    return r;
}

__device__ __forceinline__ void cp16(void* smem_ptr, const void* gptr) {
    unsigned s = (unsigned)__cvta_generic_to_shared(smem_ptr);
    asm volatile("cp.async.cg.shared.global [%0], [%1], 16;" :: "r"(s), "l"(gptr));
}

#define MMA_TF32(cc, aa, bb)                                                   \
    asm volatile(                                                              \
        "mma.sync.aligned.m16n8k8.row.col.f32.tf32.tf32.f32 "                  \
        "{%0,%1,%2,%3}, {%4,%5,%6,%7}, {%8,%9}, {%0,%1,%2,%3};"                \
        : "+f"(cc[0]), "+f"(cc[1]), "+f"(cc[2]), "+f"(cc[3])                   \
        : "r"(aa[0]), "r"(aa[1]), "r"(aa[2]), "r"(aa[3]), "r"(bb[0]), "r"(bb[1]))

#define AS_STRIDE 36
#define BS_STRIDE 136
#define GEMM_SMEM (2 * (128 * AS_STRIDE + 32 * BS_STRIDE) * 4)

// ===========================================================================
// TF32 GEMM mainloop (unchanged from the 1142us baseline).
// ===========================================================================
struct GemmFrag { float c[4][4][4]; };

__device__ __forceinline__ void gemm_mainloop(
    const float* __restrict__ A, const float* __restrict__ B,
    unsigned* As, unsigned* Bs,
    int bm, int bn, int N, int K, GemmFrag& F)
{
    const int tid  = threadIdx.x;
    const int lane = tid & 31;
    const int warp = tid >> 5;
    const int wm = (warp >> 2) * 64;
    const int wn = (warp & 3) * 32;

    const int ar = tid >> 3;
    const int ac = (tid & 7) * 4;
    const int br = tid >> 5;
    const int bc = (tid & 31) * 4;

    const float* Ag = A + (size_t)(bm + ar) * K + ac;
    const float* Bg = B + (size_t)br * N + bn + bc;

    float4 areg[4], breg[4];
#pragma unroll
    for (int i = 0; i < 4; i++) areg[i] = *(const float4*)(Ag + (size_t)(i * 32) * K);
#pragma unroll
    for (int i = 0; i < 4; i++) breg[i] = *(const float4*)(Bg + (size_t)(i * 8) * N);

#pragma unroll
    for (int mt = 0; mt < 4; mt++)
#pragma unroll
        for (int nt = 0; nt < 4; nt++)
#pragma unroll
            for (int i = 0; i < 4; i++) F.c[mt][nt][i] = 0.f;

#pragma unroll
    for (int i = 0; i < 4; i++) {
        unsigned* p = &As[(ar + i * 32) * AS_STRIDE + ac];
        p[0] = f2tf(areg[i].x); p[1] = f2tf(areg[i].y);
        p[2] = f2tf(areg[i].z); p[3] = f2tf(areg[i].w);
    }
#pragma unroll
    for (int i = 0; i < 4; i++) {
        unsigned* p = &Bs[(br + i * 8) * BS_STRIDE + bc];
        p[0] = f2tf(breg[i].x); p[1] = f2tf(breg[i].y);
        p[2] = f2tf(breg[i].z); p[3] = f2tf(breg[i].w);
    }
    __syncthreads();

    int buf = 0;
    for (int k0 = 32; k0 <= K; k0 += 32) {
        const int nbuf = buf ^ 1;
        const bool more = (k0 < K);
        if (more) {
#pragma unroll
            for (int i = 0; i < 4; i++)
                areg[i] = *(const float4*)(Ag + (size_t)(i * 32) * K + k0);
#pragma unroll
            for (int i = 0; i < 4; i++)
                breg[i] = *(const float4*)(Bg + (size_t)(k0 + i * 8) * N);
        }

        const unsigned* Ab = As + buf * 128 * AS_STRIDE;
        const unsigned* Bb = Bs + buf * 32 * BS_STRIDE;
#pragma unroll
        for (int ks = 0; ks < 4; ks++) {
            const int kk = ks * 8;
            unsigned a[4][4], b[4][2];
#pragma unroll
            for (int mt = 0; mt < 4; mt++) {
                const unsigned* ap = Ab + (wm + mt * 16 + (lane >> 2)) * AS_STRIDE + kk + (lane & 3);
                a[mt][0] = ap[0];
                a[mt][1] = ap[8 * AS_STRIDE];
                a[mt][2] = ap[4];
                a[mt][3] = ap[8 * AS_STRIDE + 4];
            }
#pragma unroll
            for (int nt = 0; nt < 4; nt++) {
                const unsigned* bp = Bb + (kk + (lane & 3)) * BS_STRIDE + wn + nt * 8 + (lane >> 2);
                b[nt][0] = bp[0];
                b[nt][1] = bp[4 * BS_STRIDE];
            }
#pragma unroll
            for (int mt = 0; mt < 4; mt++)
#pragma unroll
                for (int nt = 0; nt < 4; nt++)
                    MMA_TF32(F.c[mt][nt], a[mt], b[nt]);
        }

        if (more) {
            unsigned* An = As + nbuf * 128 * AS_STRIDE;
            unsigned* Bn = Bs + nbuf * 32 * BS_STRIDE;
#pragma unroll
            for (int i = 0; i < 4; i++) {
                unsigned* p = &An[(ar + i * 32) * AS_STRIDE + ac];
                p[0] = f2tf(areg[i].x); p[1] = f2tf(areg[i].y);
                p[2] = f2tf(areg[i].z); p[3] = f2tf(areg[i].w);
            }
#pragma unroll
            for (int i = 0; i < 4; i++) {
                unsigned* p = &Bn[(br + i * 8) * BS_STRIDE + bc];
                p[0] = f2tf(breg[i].x); p[1] = f2tf(breg[i].y);
                p[2] = f2tf(breg[i].z); p[3] = f2tf(breg[i].w);
            }
        }
        __syncthreads();
        buf = nbuf;
    }
}

__device__ __forceinline__ void gemm_store(float* __restrict__ C, int bm, int bn,
                                           int N, const GemmFrag& F) {
    const int lane = threadIdx.x & 31;
    const int warp = threadIdx.x >> 5;
    const int wm = (warp >> 2) * 64;
    const int wn = (warp & 3) * 32;
#pragma unroll
    for (int mt = 0; mt < 4; mt++)
#pragma unroll
        for (int nt = 0; nt < 4; nt++) {
            const int r0 = bm + wm + mt * 16 + (lane >> 2);
            const int cc = bn + wn + nt * 8 + (lane & 3) * 2;
            float2 v0 = {F.c[mt][nt][0], F.c[mt][nt][1]};
            float2 v1 = {F.c[mt][nt][2], F.c[mt][nt][3]};
            *(float2*)(C + (size_t)r0 * N + cc) = v0;
            *(float2*)(C + (size_t)(r0 + 8) * N + cc) = v1;
        }
}

// ===========================================================================
// Combined QKV projection GEMM (one 768-block launch).
// ===========================================================================
__global__ __launch_bounds__(256) void qkv_gemm(const float* __restrict__ x,
                                                const float* __restrict__ Wq,
                                                const float* __restrict__ Wk,
                                                const float* __restrict__ Wv,
                                                float* __restrict__ qo,
                                                float* __restrict__ ko,
                                                float* __restrict__ vo) {
    extern __shared__ unsigned sm_u[];
    unsigned* As = sm_u;
    unsigned* Bs = sm_u + 2 * 128 * AS_STRIDE;

    const int bx = blockIdx.x;
    int bm, bn, N;
    const float* Bmat;
    float* Cmat;
    if (bx < 512) {
        Bmat = Wq; Cmat = qo; N = H_ * HD_;
        bn = (bx & 15) * 128; bm = (bx >> 4) * 128;
    } else if (bx < 640) {
        const int l = bx - 512;
        Bmat = Wk; Cmat = ko; N = KV_ * HD_;
        bn = (l & 3) * 128; bm = (l >> 2) * 128;
    } else {
        const int l = bx - 640;
        Bmat = Wv; Cmat = vo; N = KV_ * HD_;
        bn = (l & 3) * 128; bm = (l >> 2) * 128;
    }

    GemmFrag F;
    gemm_mainloop(x, Bmat, As, Bs, bm, bn, N, D_, F);
    gemm_store(Cmat, bm, bn, N, F);
}

// ===========================================================================
// Plain TF32 GEMM (O projection).
// ===========================================================================
__global__ __launch_bounds__(256) void gemm_tf32(const float* __restrict__ A,
                                                 const float* __restrict__ B,
                                                 float* __restrict__ C,
                                                 int M, int N, int K) {
    extern __shared__ unsigned sm_u[];
    unsigned* As = sm_u;
    unsigned* Bs = sm_u + 2 * 128 * AS_STRIDE;

    const int bm = blockIdx.y * 128;
    const int bn = blockIdx.x * 128;

    GemmFrag F;
    gemm_mainloop(A, B, As, Bs, bm, bn, N, K, F);
    gemm_store(C, bm, bn, N, F);
}

// ---------------------------------------------------------------------------
// Fused RMSNorm + RoPE, in place (unchanged).
// ---------------------------------------------------------------------------
__global__ __launch_bounds__(256) void rmsnorm_rope_kernel(float* __restrict__ data,
                                                           const float* __restrict__ scale,
                                                           const float* __restrict__ cosT,
                                                           const float* __restrict__ sinT,
                                                           int nheads, int total_rows) {
    const int warp = threadIdx.x >> 5;
    const int lane = threadIdx.x & 31;
    const int row = blockIdx.x * 8 + warp;
    if (row >= total_rows) return;
    const int t = (row / nheads) % T_;

    float4* p = (float4*)(data + (size_t)row * HD_);
    float4 x = p[lane];
    float ss = x.x * x.x + x.y * x.y + x.z * x.z + x.w * x.w;
#pragma unroll
    for (int o = 16; o > 0; o >>= 1) ss += __shfl_xor_sync(0xffffffffu, ss, o);
    const float rinv = rsqrtf(ss * (1.0f / HD_) + 1e-6f);

    const int d0 = lane * 4;
    float4 sc = *(const float4*)(scale + d0);
    float n0 = x.x * rinv * sc.x;
    float n1 = x.y * rinv * sc.y;
    float n2 = x.z * rinv * sc.z;
    float n3 = x.w * rinv * sc.w;

    const float c0 = cosT[(size_t)t * HD_ + d0];
    const float s0 = sinT[(size_t)t * HD_ + d0];
    const float c1 = cosT[(size_t)t * HD_ + d0 + 2];
    const float s1 = sinT[(size_t)t * HD_ + d0 + 2];

    float4 r;
    r.x = n0 * c0 - n1 * s0;
    r.y = n1 * c0 + n0 * s0;
    r.z = n2 * c1 - n3 * s1;
    r.w = n3 * c1 + n2 * s1;
    p[lane] = r;
}

// ---------------------------------------------------------------------------
// Tensor-core causal GQA flash attention, cp.async pipelined.
// Block: 256 thr = 8 warps; 128 query rows/block (16 per warp).
// K/V: 32-key tiles, raw fp32, double-buffered via cp.async (tf32 cvt at
// fragment load). Q: tf32 in smem. One wait+sync per tile.
// ---------------------------------------------------------------------------
#define FA_PAD  132   // row stride (u32/float) for Qs/Ks/Vs
#define FA_PPAD 36    // row stride (u32) for per-warp P buffer
#define FA_KT   32    // keys per tile
// smem (u32): Q 128*132 | K 2*32*132 | V 2*32*132 | P 8*16*36
#define FA_Q_OFF 0
#define FA_K_OFF (128 * FA_PAD)
#define FA_V_OFF (FA_K_OFF + 2 * 32 * FA_PAD)
#define FA_P_OFF (FA_V_OFF + 2 * 32 * FA_PAD)
#define FA_SMEM ((FA_P_OFF + 8 * 16 * FA_PPAD) * 4)

__global__ __launch_bounds__(256, 1) void flash_tc(const float* __restrict__ q,
                                                   const float* __restrict__ k,
                                                   const float* __restrict__ v,
                                                   float* __restrict__ o) {
    extern __shared__ unsigned fsm[];
    unsigned* Qs = fsm + FA_Q_OFF;
    float* Ksf = (float*)(fsm + FA_K_OFF);
    float* Vsf = (float*)(fsm + FA_V_OFF);
    unsigned* Psw = fsm + FA_P_OFF + (threadIdx.x >> 5) * 16 * FA_PPAD;

    const int tid  = threadIdx.x;
    const int warp = tid >> 5;
    const int lane = tid & 31;
    const int la3  = lane & 3;
    const int r    = lane >> 2;
    const int bh = blockIdx.y;
    const int b = bh >> 4;
    const int h = bh & 15;
    const int g = h >> 2;
    const int qb = (gridDim.x - 1) - blockIdx.x;   // heavy tiles first
    const int qbase = qb * 128;
    const int wm = warp * 16;
    const size_t bT = (size_t)b * T_;

    const float sscale = 0.08838834764831845f;  // 1/sqrt(128)
    const int ntiles = (qb + 1) * (128 / FA_KT);

    // Prefetch K/V tile 0 into buffer 0 (cp.async), then stage Q.
    {
        for (int i = tid; i < FA_KT * 32; i += 256) {
            const int row = i >> 5, c4 = (i & 31) * 4;
            const size_t gi = ((bT + row) * KV_ + g) * HD_ + c4;
            cp16(&Ksf[row * FA_PAD + c4], k + gi);
            cp16(&Vsf[row * FA_PAD + c4], v + gi);
        }
        asm volatile("cp.async.commit_group;" ::: "memory");
    }

    // Load Q tile (128 x 128), fold in score scale, cvt tf32
    for (int i = tid; i < 128 * 32; i += 256) {
        const int row = i >> 5, c4 = (i & 31) * 4;
        float4 t = *(const float4*)(q + ((bT + qbase + row) * H_ + h) * HD_ + c4);
        uint4 u = {f2tf(t.x * sscale), f2tf(t.y * sscale), f2tf(t.z * sscale), f2tf(t.w * sscale)};
        *(uint4*)&Qs[row * FA_PAD + c4] = u;
    }

    float m0 = -1e30f, m1 = -1e30f, l0 = 0.f, l1 = 0.f;
    float acc[16][4];
#pragma unroll
    for (int ns = 0; ns < 16; ns++)
#pragma unroll
        for (int i = 0; i < 4; i++) acc[ns][i] = 0.f;

    const int row0 = qbase + wm + r;   // global q row for c-frag row 0

    for (int j = 0; j < ntiles; j++) {
        const int kbase = j * FA_KT;
        const int buf = (j & 1) * FA_KT * FA_PAD;

        asm volatile("cp.async.wait_group 0;" ::: "memory");
        __syncthreads();

        // Prefetch next tile into the other buffer.
        if (j + 1 < ntiles) {
            const int nb = ((j + 1) & 1) * FA_KT * FA_PAD;
            const int nkb = kbase + FA_KT;
            for (int i = tid; i < FA_KT * 32; i += 256) {
                const int row = i >> 5, c4 = (i & 31) * 4;
                const size_t gi = ((bT + nkb + row) * KV_ + g) * HD_ + c4;
                cp16(&Ksf[nb + row * FA_PAD + c4], k + gi);
                cp16(&Vsf[nb + row * FA_PAD + c4], v + gi);
            }
            asm volatile("cp.async.commit_group;" ::: "memory");
        }

        const bool active = (kbase <= qbase + wm + 15);
        if (active) {
            // S = Q . K^T  (16 x 32 per warp)
            float s[4][4];
#pragma unroll
            for (int ns = 0; ns < 4; ns++)
#pragma unroll
                for (int i = 0; i < 4; i++) s[ns][i] = 0.f;

#pragma unroll
            for (int kc = 0; kc < 16; kc++) {
                unsigned a[4];
                const unsigned* ap = Qs + (wm + r) * FA_PAD + kc * 8 + la3;
                a[0] = ap[0];
                a[1] = ap[8 * FA_PAD];
                a[2] = ap[4];
                a[3] = ap[8 * FA_PAD + 4];
#pragma unroll
                for (int ns = 0; ns < 4; ns++) {
                    const float* bp = Ksf + buf + (ns * 8 + r) * FA_PAD + kc * 8 + la3;
                    unsigned bf[2];
                    bf[0] = f2tf(bp[0]);
                    bf[1] = f2tf(bp[4]);
                    MMA_TF32(s[ns], a, bf);
                }
            }

            // causal mask (only near the diagonal)
            if (kbase + FA_KT - 1 > qbase + wm) {
#pragma unroll
                for (int ns = 0; ns < 4; ns++) {
                    const int col = kbase + ns * 8 + la3 * 2;
                    if (col > row0)     s[ns][0] = -1e30f;
                    if (col + 1 > row0) s[ns][1] = -1e30f;
                    if (col > row0 + 8)     s[ns][2] = -1e30f;
                    if (col + 1 > row0 + 8) s[ns][3] = -1e30f;
                }
            }

            // online softmax (warp-local; quad reductions)
            float mx0 = -1e30f, mx1 = -1e30f;
#pragma unroll
            for (int ns = 0; ns < 4; ns++) {
                mx0 = fmaxf(mx0, fmaxf(s[ns][0], s[ns][1]));
                mx1 = fmaxf(mx1, fmaxf(s[ns][2], s[ns][3]));
            }
            mx0 = fmaxf(mx0, __shfl_xor_sync(0xffffffffu, mx0, 1));
            mx0 = fmaxf(mx0, __shfl_xor_sync(0xffffffffu, mx0, 2));
            mx1 = fmaxf(mx1, __shfl_xor_sync(0xffffffffu, mx1, 1));
            mx1 = fmaxf(mx1, __shfl_xor_sync(0xffffffffu, mx1, 2));

            const float mn0 = fmaxf(m0, mx0);
            const float mn1 = fmaxf(m1, mx1);
            const float al0 = __expf(m0 - mn0);
            const float al1 = __expf(m1 - mn1);
            m0 = mn0; m1 = mn1;

            float sum0 = 0.f, sum1 = 0.f;
#pragma unroll
            for (int ns = 0; ns < 4; ns++) {
                float p0 = __expf(s[ns][0] - mn0);
                float p1 = __expf(s[ns][1] - mn0);
                float p2 = __expf(s[ns][2] - mn1);
                float p3 = __expf(s[ns][3] - mn1);
                sum0 += p0 + p1;
                sum1 += p2 + p3;
                uint2 u0 = {f2tf(p0), f2tf(p1)};
                uint2 u1 = {f2tf(p2), f2tf(p3)};
                *(uint2*)&Psw[r * FA_PPAD + ns * 8 + la3 * 2] = u0;
                *(uint2*)&Psw[(r + 8) * FA_PPAD + ns * 8 + la3 * 2] = u1;
            }
            sum0 += __shfl_xor_sync(0xffffffffu, sum0, 1);
            sum0 += __shfl_xor_sync(0xffffffffu, sum0, 2);
            sum1 += __shfl_xor_sync(0xffffffffu, sum1, 1);
            sum1 += __shfl_xor_sync(0xffffffffu, sum1, 2);
            l0 = l0 * al0 + sum0;
            l1 = l1 * al1 + sum1;

#pragma unroll
            for (int ns = 0; ns < 16; ns++) {
                acc[ns][0] *= al0; acc[ns][1] *= al0;
                acc[ns][2] *= al1; acc[ns][3] *= al1;
            }
            __syncwarp();

            // O += P . V   (P: 16x32, V: 32x128)
#pragma unroll
            for (int kc = 0; kc < 4; kc++) {
                unsigned a[4];
                const unsigned* ap = Psw + r * FA_PPAD + kc * 8 + la3;
                a[0] = ap[0];
                a[1] = ap[8 * FA_PPAD];
                a[2] = ap[4];
                a[3] = ap[8 * FA_PPAD + 4];
#pragma unroll
                for (int ns = 0; ns < 16; ns++) {
                    const float* bp = Vsf + buf + (kc * 8 + la3) * FA_PAD + ns * 8 + r;
                    unsigned bf[2];
                    bf[0] = f2tf(bp[0]);
                    bf[1] = f2tf(bp[4 * FA_PAD]);
                    MMA_TF32(acc[ns], a, bf);
                }
            }
        }
    }

    // epilogue
    const float inv0 = 1.0f / l0;
    const float inv1 = 1.0f / l1;
    float* o0 = o + ((bT + row0) * H_ + h) * HD_;
    float* o1 = o + ((bT + row0 + 8) * H_ + h) * HD_;
#pragma unroll
    for (int ns = 0; ns < 16; ns++) {
        const int col = ns * 8 + la3 * 2;
        float2 v0 = {acc[ns][0] * inv0, acc[ns][1] * inv0};
        float2 v1 = {acc[ns][2] * inv1, acc[ns][3] * inv1};
        *(float2*)(o0 + col) = v0;
        *(float2*)(o1 + col) = v1;
    }
}

// ---------------------------------------------------------------------------
extern "C" void kernel_launch(void* const* d_in, const int* in_sizes, int n_in,
                              void* d_out, int out_size) {
    const float* x       = (const float*)d_in[0];
    const float* Wq      = (const float*)d_in[1];
    const float* Wk      = (const float*)d_in[2];
    const float* Wv      = (const float*)d_in[3];
    const float* Wo      = (const float*)d_in[4];
    const float* q_scale = (const float*)d_in[5];
    const float* k_scale = (const float*)d_in[6];
    const float* cosT    = (const float*)d_in[7];
    const float* sinT    = (const float*)d_in[8];
    float* out = (float*)d_out;

    float *q, *k, *v, *ao;
    cudaGetSymbolAddress((void**)&q,  g_q);
    cudaGetSymbolAddress((void**)&k,  g_k);
    cudaGetSymbolAddress((void**)&v,  g_v);
    cudaGetSymbolAddress((void**)&ao, g_o);

    const int M = B_ * T_;  // 4096

    cudaFuncSetAttribute(qkv_gemm, cudaFuncAttributeMaxDynamicSharedMemorySize, GEMM_SMEM);
    cudaFuncSetAttribute(gemm_tf32, cudaFuncAttributeMaxDynamicSharedMemorySize, GEMM_SMEM);
    cudaFuncSetAttribute(flash_tc, cudaFuncAttributeMaxDynamicSharedMemorySize, FA_SMEM);

    // Combined QKV projections (one launch, 768 blocks)
    qkv_gemm<<<768, 256, GEMM_SMEM>>>(x, Wq, Wk, Wv, q, k, v);

    // RMSNorm + RoPE on q and k (in place)
    rmsnorm_rope_kernel<<<(M * H_) / 8, 256>>>(q, q_scale, cosT, sinT, H_, M * H_);
    rmsnorm_rope_kernel<<<(M * KV_) / 8, 256>>>(k, k_scale, cosT, sinT, KV_, M * KV_);

    // Tensor-core flash attention (cp.async pipelined)
    flash_tc<<<dim3(T_ / 128, B_ * H_), 256, FA_SMEM>>>(q, k, v, ao);

    // Output projection
    gemm_tf32<<<dim3(D_ / 128, M / 128), 256, GEMM_SMEM>>>(ao, Wo, out, M, D_, H_ * HD_);
}

// round 12
// speedup vs baseline: 1.2689x; 1.2689x over previous
#include <cuda_runtime.h>
#include <cuda_fp16.h>
#include <math.h>

#define B_  2
#define T_  2048
#define D_  2048
#define H_  16
#define KV_ 4
#define HD_ 128

// Scratch (allocation-free rule: __device__ globals)
__device__ float  g_q [(size_t)B_ * T_ * H_  * HD_];   // fp32 q (pre-norm)
__device__ float  g_k [(size_t)B_ * T_ * KV_ * HD_];   // fp32 k (pre-norm)
__device__ __half g_qh[(size_t)B_ * T_ * H_  * HD_];   // half q (normed+rope+scaled)
__device__ __half g_kh[(size_t)B_ * T_ * KV_ * HD_];   // half k (normed+rope)
__device__ __half g_vt[(size_t)B_ * KV_ * HD_ * T_];   // half V transposed [b,g,hd,t]
__device__ float  g_o [(size_t)B_ * T_ * H_  * HD_];   // attention output

__device__ __forceinline__ unsigned f2tf(float x) {
    unsigned r;
    asm("cvt.rna.tf32.f32 %0, %1;" : "=r"(r) : "f"(x));
    return r;
}

__device__ __forceinline__ void cp16(void* smem_ptr, const void* gptr) {
    unsigned s = (unsigned)__cvta_generic_to_shared(smem_ptr);
    asm volatile("cp.async.cg.shared.global [%0], [%1], 16;" :: "r"(s), "l"(gptr));
}

#define MMA_TF32(cc, aa, bb)                                                   \
    asm volatile(                                                              \
        "mma.sync.aligned.m16n8k8.row.col.f32.tf32.tf32.f32 "                  \
        "{%0,%1,%2,%3}, {%4,%5,%6,%7}, {%8,%9}, {%0,%1,%2,%3};"                \
        : "+f"(cc[0]), "+f"(cc[1]), "+f"(cc[2]), "+f"(cc[3])                   \
        : "r"(aa[0]), "r"(aa[1]), "r"(aa[2]), "r"(aa[3]), "r"(bb[0]), "r"(bb[1]))

#define MMA_F16(cc, aa, bb)                                                    \
    asm volatile(                                                              \
        "mma.sync.aligned.m16n8k16.row.col.f32.f16.f16.f32 "                   \
        "{%0,%1,%2,%3}, {%4,%5,%6,%7}, {%8,%9}, {%0,%1,%2,%3};"                \
        : "+f"(cc[0]), "+f"(cc[1]), "+f"(cc[2]), "+f"(cc[3])                   \
        : "r"(aa[0]), "r"(aa[1]), "r"(aa[2]), "r"(aa[3]), "r"(bb[0]), "r"(bb[1]))

#define AS_STRIDE 36
#define BS_STRIDE 136
#define GEMM_SMEM (2 * (128 * AS_STRIDE + 32 * BS_STRIDE) * 4)

// ===========================================================================
// TF32 GEMM mainloop (unchanged from 1142us baseline).
// ===========================================================================
struct GemmFrag { float c[4][4][4]; };

__device__ __forceinline__ void gemm_mainloop(
    const float* __restrict__ A, const float* __restrict__ B,
    unsigned* As, unsigned* Bs,
    int bm, int bn, int N, int K, GemmFrag& F)
{
    const int tid  = threadIdx.x;
    const int lane = tid & 31;
    const int warp = tid >> 5;
    const int wm = (warp >> 2) * 64;
    const int wn = (warp & 3) * 32;

    const int ar = tid >> 3;
    const int ac = (tid & 7) * 4;
    const int br = tid >> 5;
    const int bc = (tid & 31) * 4;

    const float* Ag = A + (size_t)(bm + ar) * K + ac;
    const float* Bg = B + (size_t)br * N + bn + bc;

    float4 areg[4], breg[4];
#pragma unroll
    for (int i = 0; i < 4; i++) areg[i] = *(const float4*)(Ag + (size_t)(i * 32) * K);
#pragma unroll
    for (int i = 0; i < 4; i++) breg[i] = *(const float4*)(Bg + (size_t)(i * 8) * N);

#pragma unroll
    for (int mt = 0; mt < 4; mt++)
#pragma unroll
        for (int nt = 0; nt < 4; nt++)
#pragma unroll
            for (int i = 0; i < 4; i++) F.c[mt][nt][i] = 0.f;

#pragma unroll
    for (int i = 0; i < 4; i++) {
        unsigned* p = &As[(ar + i * 32) * AS_STRIDE + ac];
        p[0] = f2tf(areg[i].x); p[1] = f2tf(areg[i].y);
        p[2] = f2tf(areg[i].z); p[3] = f2tf(areg[i].w);
    }
#pragma unroll
    for (int i = 0; i < 4; i++) {
        unsigned* p = &Bs[(br + i * 8) * BS_STRIDE + bc];
        p[0] = f2tf(breg[i].x); p[1] = f2tf(breg[i].y);
        p[2] = f2tf(breg[i].z); p[3] = f2tf(breg[i].w);
    }
    __syncthreads();

    int buf = 0;
    for (int k0 = 32; k0 <= K; k0 += 32) {
        const int nbuf = buf ^ 1;
        const bool more = (k0 < K);
        if (more) {
#pragma unroll
            for (int i = 0; i < 4; i++)
                areg[i] = *(const float4*)(Ag + (size_t)(i * 32) * K + k0);
#pragma unroll
            for (int i = 0; i < 4; i++)
                breg[i] = *(const float4*)(Bg + (size_t)(k0 + i * 8) * N);
        }

        const unsigned* Ab = As + buf * 128 * AS_STRIDE;
        const unsigned* Bb = Bs + buf * 32 * BS_STRIDE;
#pragma unroll
        for (int ks = 0; ks < 4; ks++) {
            const int kk = ks * 8;
            unsigned a[4][4], b[4][2];
#pragma unroll
            for (int mt = 0; mt < 4; mt++) {
                const unsigned* ap = Ab + (wm + mt * 16 + (lane >> 2)) * AS_STRIDE + kk + (lane & 3);
                a[mt][0] = ap[0];
                a[mt][1] = ap[8 * AS_STRIDE];
                a[mt][2] = ap[4];
                a[mt][3] = ap[8 * AS_STRIDE + 4];
            }
#pragma unroll
            for (int nt = 0; nt < 4; nt++) {
                const unsigned* bp = Bb + (kk + (lane & 3)) * BS_STRIDE + wn + nt * 8 + (lane >> 2);
                b[nt][0] = bp[0];
                b[nt][1] = bp[4 * BS_STRIDE];
            }
#pragma unroll
            for (int mt = 0; mt < 4; mt++)
#pragma unroll
                for (int nt = 0; nt < 4; nt++)
                    MMA_TF32(F.c[mt][nt], a[mt], b[nt]);
        }

        if (more) {
            unsigned* An = As + nbuf * 128 * AS_STRIDE;
            unsigned* Bn = Bs + nbuf * 32 * BS_STRIDE;
#pragma unroll
            for (int i = 0; i < 4; i++) {
                unsigned* p = &An[(ar + i * 32) * AS_STRIDE + ac];
                p[0] = f2tf(areg[i].x); p[1] = f2tf(areg[i].y);
                p[2] = f2tf(areg[i].z); p[3] = f2tf(areg[i].w);
            }
#pragma unroll
            for (int i = 0; i < 4; i++) {
                unsigned* p = &Bn[(br + i * 8) * BS_STRIDE + bc];
                p[0] = f2tf(breg[i].x); p[1] = f2tf(breg[i].y);
                p[2] = f2tf(breg[i].z); p[3] = f2tf(breg[i].w);
            }
        }
        __syncthreads();
        buf = nbuf;
    }
}

__device__ __forceinline__ void gemm_store(float* __restrict__ C, int bm, int bn,
                                           int N, const GemmFrag& F) {
    const int lane = threadIdx.x & 31;
    const int warp = threadIdx.x >> 5;
    const int wm = (warp >> 2) * 64;
    const int wn = (warp & 3) * 32;
#pragma unroll
    for (int mt = 0; mt < 4; mt++)
#pragma unroll
        for (int nt = 0; nt < 4; nt++) {
            const int r0 = bm + wm + mt * 16 + (lane >> 2);
            const int cc = bn + wn + nt * 8 + (lane & 3) * 2;
            float2 v0 = {F.c[mt][nt][0], F.c[mt][nt][1]};
            float2 v1 = {F.c[mt][nt][2], F.c[mt][nt][3]};
            *(float2*)(C + (size_t)r0 * N + cc) = v0;
            *(float2*)(C + (size_t)(r0 + 8) * N + cc) = v1;
        }
}

// ===========================================================================
// Combined QKV projection GEMM. q,k -> fp32 scratch; v -> half TRANSPOSED
// [b, g, hd, t] so flash can cp.async it directly as PV mma B operand.
// grid.x = 768: [0,512) q, [512,640) k, [640,768) v.
// ===========================================================================
__global__ __launch_bounds__(256) void qkv_gemm(const float* __restrict__ x,
                                                const float* __restrict__ Wq,
                                                const float* __restrict__ Wk,
                                                const float* __restrict__ Wv,
                                                float* __restrict__ qo,
                                                float* __restrict__ ko,
                                                __half* __restrict__ vt) {
    extern __shared__ unsigned sm_u[];
    unsigned* As = sm_u;
    unsigned* Bs = sm_u + 2 * 128 * AS_STRIDE;

    const int bx = blockIdx.x;
    int bm, bn, N, seg;
    const float* Bmat;
    float* Cmat = 0;
    if (bx < 512) {
        seg = 0; Bmat = Wq; Cmat = qo; N = H_ * HD_;
        bn = (bx & 15) * 128; bm = (bx >> 4) * 128;
    } else if (bx < 640) {
        const int l = bx - 512;
        seg = 1; Bmat = Wk; Cmat = ko; N = KV_ * HD_;
        bn = (l & 3) * 128; bm = (l >> 2) * 128;
    } else {
        const int l = bx - 640;
        seg = 2; Bmat = Wv; N = KV_ * HD_;
        bn = (l & 3) * 128; bm = (l >> 2) * 128;
    }

    GemmFrag F;
    gemm_mainloop(x, Bmat, As, Bs, bm, bn, N, D_, F);

    if (seg != 2) {
        gemm_store(Cmat, bm, bn, N, F);
        return;
    }

    // v epilogue: half, transposed to [b, g, hd, t]
    const int lane = threadIdx.x & 31;
    const int warp = threadIdx.x >> 5;
    const int wm = (warp >> 2) * 64;
    const int wn = (warp & 3) * 32;
    const int r  = lane >> 2;
    const int la3 = lane & 3;
#pragma unroll
    for (int mt = 0; mt < 4; mt++) {
        const int r0 = bm + wm + mt * 16 + r;
        const int b0 = r0 >> 11;            // T_ = 2048
        const int t0 = r0 & (T_ - 1);
#pragma unroll
        for (int nt = 0; nt < 4; nt++) {
            const int col = bn + wn + nt * 8 + la3 * 2;
            const int g  = col >> 7;
            const int hd = col & 127;
            __half* dst = vt + ((size_t)(b0 * KV_ + g) * HD_ + hd) * T_;
            dst[t0]            = __float2half_rn(F.c[mt][nt][0]);
            dst[T_ + t0]       = __float2half_rn(F.c[mt][nt][1]);
            dst[t0 + 8]        = __float2half_rn(F.c[mt][nt][2]);
            dst[T_ + t0 + 8]   = __float2half_rn(F.c[mt][nt][3]);
        }
    }
}

// ===========================================================================
// Plain TF32 GEMM (O projection).
// ===========================================================================
__global__ __launch_bounds__(256) void gemm_tf32(const float* __restrict__ A,
                                                 const float* __restrict__ B,
                                                 float* __restrict__ C,
                                                 int M, int N, int K) {
    extern __shared__ unsigned sm_u[];
    unsigned* As = sm_u;
    unsigned* Bs = sm_u + 2 * 128 * AS_STRIDE;

    const int bm = blockIdx.y * 128;
    const int bn = blockIdx.x * 128;

    GemmFrag F;
    gemm_mainloop(A, B, As, Bs, bm, bn, N, K, F);
    gemm_store(C, bm, bn, N, F);
}

// ---------------------------------------------------------------------------
// RMSNorm + RoPE; reads fp32, writes HALF (fold multiplies all outputs).
// ---------------------------------------------------------------------------
__global__ __launch_bounds__(256) void rmsnorm_rope_h(const float* __restrict__ in,
                                                      __half* __restrict__ outp,
                                                      const float* __restrict__ scale,
                                                      const float* __restrict__ cosT,
                                                      const float* __restrict__ sinT,
                                                      int nheads, int total_rows,
                                                      float fold) {
    const int warp = threadIdx.x >> 5;
    const int lane = threadIdx.x & 31;
    const int row = blockIdx.x * 8 + warp;
    if (row >= total_rows) return;
    const int t = (row / nheads) % T_;

    const float4* p = (const float4*)(in + (size_t)row * HD_);
    float4 x = p[lane];
    float ss = x.x * x.x + x.y * x.y + x.z * x.z + x.w * x.w;
#pragma unroll
    for (int o = 16; o > 0; o >>= 1) ss += __shfl_xor_sync(0xffffffffu, ss, o);
    const float rinv = rsqrtf(ss * (1.0f / HD_) + 1e-6f);

    const int d0 = lane * 4;
    float4 sc = *(const float4*)(scale + d0);
    float n0 = x.x * rinv * sc.x;
    float n1 = x.y * rinv * sc.y;
    float n2 = x.z * rinv * sc.z;
    float n3 = x.w * rinv * sc.w;

    const float c0 = cosT[(size_t)t * HD_ + d0];
    const float s0 = sinT[(size_t)t * HD_ + d0];
    const float c1 = cosT[(size_t)t * HD_ + d0 + 2];
    const float s1 = sinT[(size_t)t * HD_ + d0 + 2];

    const float o0 = (n0 * c0 - n1 * s0) * fold;
    const float o1 = (n1 * c0 + n0 * s0) * fold;
    const float o2 = (n2 * c1 - n3 * s1) * fold;
    const float o3 = (n3 * c1 + n2 * s1) * fold;

    __half2* q2 = (__half2*)(outp + (size_t)row * HD_ + d0);
    q2[0] = __floats2half2_rn(o0, o1);
    q2[1] = __floats2half2_rn(o2, o3);
}

// ---------------------------------------------------------------------------
// FP16 tensor-core causal GQA flash attention, cp.async pipelined, occ=2.
// Block: 256 thr = 8 warps; 128 q rows (16/warp); 32-key K/V tiles.
// m16n8k16; P stays in registers (QK c-frag == PV a-frag layout).
// smem: Q[128][136]h | K[2][32][136]h | Vt[2][128][40]h  = 71 KB.
// ---------------------------------------------------------------------------
#define FQ_STR 136
#define FV_STR 40
#define FK_HALF (128 * FQ_STR)
#define FV_HALF (FK_HALF + 2 * 32 * FQ_STR)
#define FA_SMEM ((FV_HALF + 2 * 128 * FV_STR) * 2)

__global__ __launch_bounds__(256, 2) void flash_f16(const __half* __restrict__ qh,
                                                    const __half* __restrict__ kh,
                                                    const __half* __restrict__ vt,
                                                    float* __restrict__ o) {
    extern __shared__ __half hsm[];
    __half* Qs = hsm;
    __half* Ks = hsm + FK_HALF;
    __half* Vs = hsm + FV_HALF;
    const unsigned* Qw = (const unsigned*)Qs;
    const unsigned* Kw = (const unsigned*)Ks;
    const unsigned* Vw = (const unsigned*)Vs;

    const int tid  = threadIdx.x;
    const int warp = tid >> 5;
    const int lane = tid & 31;
    const int la3  = lane & 3;
    const int r    = lane >> 2;
    const int bh = blockIdx.y;
    const int b = bh >> 4;
    const int h = bh & 15;
    const int g = h >> 2;
    const int qb = (gridDim.x - 1) - blockIdx.x;   // heavy tiles first
    const int qbase = qb * 128;
    const int wm = warp * 16;
    const size_t bT = (size_t)b * T_;
    const __half* vbase = vt + (size_t)(b * KV_ + g) * HD_ * T_;

    const int ntiles = (qb + 1) * 4;   // 32-key tiles

    // Prefetch group 0: Q tile + K/V tile 0.
    for (int i = tid; i < 2048; i += 256) {          // Q: 128 rows x 16 chunks
        const int row = i >> 4, ch = (i & 15) * 8;
        cp16(&Qs[row * FQ_STR + ch], qh + ((bT + qbase + row) * H_ + h) * HD_ + ch);
    }
    for (int i = tid; i < 512; i += 256) {           // K: 32 rows x 16 chunks
        const int row = i >> 4, ch = (i & 15) * 8;
        cp16(&Ks[row * FQ_STR + ch], kh + ((bT + row) * KV_ + g) * HD_ + ch);
    }
    for (int i = tid; i < 512; i += 256) {           // V: 128 hd x 4 chunks
        const int hd = i >> 2, ch = (i & 3) * 8;
        cp16(&Vs[hd * FV_STR + ch], vbase + (size_t)hd * T_ + ch);
    }
    asm volatile("cp.async.commit_group;" ::: "memory");

    float m0 = -1e30f, m1 = -1e30f, l0 = 0.f, l1 = 0.f;
    float acc[16][4];
#pragma unroll
    for (int ns = 0; ns < 16; ns++)
#pragma unroll
        for (int i = 0; i < 4; i++) acc[ns][i] = 0.f;

    const int row0 = qbase + wm + r;

    for (int j = 0; j < ntiles; j++) {
        const int kbase = j * 32;
        const int kbw = (j & 1) * 32 * (FQ_STR / 2);   // word offsets
        const int vbw = (j & 1) * 128 * (FV_STR / 2);

        asm volatile("cp.async.wait_group 0;" ::: "memory");
        __syncthreads();

        if (j + 1 < ntiles) {
            __half* Kn = Ks + ((j + 1) & 1) * 32 * FQ_STR;
            __half* Vn = Vs + ((j + 1) & 1) * 128 * FV_STR;
            const int nkb = kbase + 32;
            for (int i = tid; i < 512; i += 256) {
                const int row = i >> 4, ch = (i & 15) * 8;
                cp16(&Kn[row * FQ_STR + ch], kh + ((bT + nkb + row) * KV_ + g) * HD_ + ch);
            }
            for (int i = tid; i < 512; i += 256) {
                const int hd = i >> 2, ch = (i & 3) * 8;
                cp16(&Vn[hd * FV_STR + ch], vbase + (size_t)hd * T_ + nkb + ch);
            }
            asm volatile("cp.async.commit_group;" ::: "memory");
        }

        const bool active = (kbase <= qbase + wm + 15);
        if (active) {
            // S = Q.K^T  (16 x 32 per warp), fp16 m16n8k16
            float s[4][4];
#pragma unroll
            for (int ns = 0; ns < 4; ns++)
#pragma unroll
                for (int i = 0; i < 4; i++) s[ns][i] = 0.f;

#pragma unroll
            for (int kc = 0; kc < 8; kc++) {
                unsigned a[4];
                const unsigned* ap = Qw + (wm + r) * (FQ_STR / 2) + kc * 8 + la3;
                a[0] = ap[0];
                a[1] = ap[8 * (FQ_STR / 2)];
                a[2] = ap[4];
                a[3] = ap[8 * (FQ_STR / 2) + 4];
#pragma unroll
                for (int ns = 0; ns < 4; ns++) {
                    const unsigned* bp = Kw + kbw + (ns * 8 + r) * (FQ_STR / 2) + kc * 8 + la3;
                    unsigned bf[2];
                    bf[0] = bp[0];
                    bf[1] = bp[4];
                    MMA_F16(s[ns], a, bf);
                }
            }

            // causal mask (near diagonal only)
            if (kbase + 31 > qbase + wm) {
#pragma unroll
                for (int ns = 0; ns < 4; ns++) {
                    const int col = kbase + ns * 8 + la3 * 2;
                    if (col > row0)     s[ns][0] = -1e30f;
                    if (col + 1 > row0) s[ns][1] = -1e30f;
                    if (col > row0 + 8)     s[ns][2] = -1e30f;
                    if (col + 1 > row0 + 8) s[ns][3] = -1e30f;
                }
            }

            // online softmax (quad-local)
            float mx0 = -1e30f, mx1 = -1e30f;
#pragma unroll
            for (int ns = 0; ns < 4; ns++) {
                mx0 = fmaxf(mx0, fmaxf(s[ns][0], s[ns][1]));
                mx1 = fmaxf(mx1, fmaxf(s[ns][2], s[ns][3]));
            }
            mx0 = fmaxf(mx0, __shfl_xor_sync(0xffffffffu, mx0, 1));
            mx0 = fmaxf(mx0, __shfl_xor_sync(0xffffffffu, mx0, 2));
            mx1 = fmaxf(mx1, __shfl_xor_sync(0xffffffffu, mx1, 1));
            mx1 = fmaxf(mx1, __shfl_xor_sync(0xffffffffu, mx1, 2));

            const float mn0 = fmaxf(m0, mx0);
            const float mn1 = fmaxf(m1, mx1);
            const float al0 = __expf(m0 - mn0);
            const float al1 = __expf(m1 - mn1);
            m0 = mn0; m1 = mn1;

            float p[4][4];
            float sum0 = 0.f, sum1 = 0.f;
#pragma unroll
            for (int ns = 0; ns < 4; ns++) {
                p[ns][0] = __expf(s[ns][0] - mn0);
                p[ns][1] = __expf(s[ns][1] - mn0);
                p[ns][2] = __expf(s[ns][2] - mn1);
                p[ns][3] = __expf(s[ns][3] - mn1);
                sum0 += p[ns][0] + p[ns][1];
                sum1 += p[ns][2] + p[ns][3];
            }
            sum0 += __shfl_xor_sync(0xffffffffu, sum0, 1);
            sum0 += __shfl_xor_sync(0xffffffffu, sum0, 2);
            sum1 += __shfl_xor_sync(0xffffffffu, sum1, 1);
            sum1 += __shfl_xor_sync(0xffffffffu, sum1, 2);
            l0 = l0 * al0 + sum0;
            l1 = l1 * al1 + sum1;

#pragma unroll
            for (int ns = 0; ns < 16; ns++) {
                acc[ns][0] *= al0; acc[ns][1] *= al0;
                acc[ns][2] *= al1; acc[ns][3] *= al1;
            }

            // O += P.V : P a-frags packed in registers from the S c-frags.
#pragma unroll
            for (int kc = 0; kc < 2; kc++) {
                unsigned a[4];
                __half2 h0 = __floats2half2_rn(p[2 * kc][0],     p[2 * kc][1]);
                __half2 h1 = __floats2half2_rn(p[2 * kc][2],     p[2 * kc][3]);
                __half2 h2 = __floats2half2_rn(p[2 * kc + 1][0], p[2 * kc + 1][1]);
                __half2 h3 = __floats2half2_rn(p[2 * kc + 1][2], p[2 * kc + 1][3]);
                a[0] = *(unsigned*)&h0;
                a[1] = *(unsigned*)&h1;
                a[2] = *(unsigned*)&h2;
                a[3] = *(unsigned*)&h3;
#pragma unroll
                for (int ns = 0; ns < 16; ns++) {
                    const unsigned* bp = Vw + vbw + (ns * 8 + r) * (FV_STR / 2) + kc * 8 + la3;
                    unsigned bf[2];
                    bf[0] = bp[0];
                    bf[1] = bp[4];
                    MMA_F16(acc[ns], a, bf);
                }
            }
        }
    }

    // epilogue (fp32 out)
    const float inv0 = 1.0f / l0;
    const float inv1 = 1.0f / l1;
    float* o0 = o + ((bT + row0) * H_ + h) * HD_;
    float* o1 = o + ((bT + row0 + 8) * H_ + h) * HD_;
#pragma unroll
    for (int ns = 0; ns < 16; ns++) {
        const int col = ns * 8 + la3 * 2;
        float2 v0 = {acc[ns][0] * inv0, acc[ns][1] * inv0};
        float2 v1 = {acc[ns][2] * inv1, acc[ns][3] * inv1};
        *(float2*)(o0 + col) = v0;
        *(float2*)(o1 + col) = v1;
    }
}

// ---------------------------------------------------------------------------
extern "C" void kernel_launch(void* const* d_in, const int* in_sizes, int n_in,
                              void* d_out, int out_size) {
    const float* x       = (const float*)d_in[0];
    const float* Wq      = (const float*)d_in[1];
    const float* Wk      = (const float*)d_in[2];
    const float* Wv      = (const float*)d_in[3];
    const float* Wo      = (const float*)d_in[4];
    const float* q_scale = (const float*)d_in[5];
    const float* k_scale = (const float*)d_in[6];
    const float* cosT    = (const float*)d_in[7];
    const float* sinT    = (const float*)d_in[8];
    float* out = (float*)d_out;

    float *q, *k, *ao;
    __half *qhp, *khp, *vtp;
    cudaGetSymbolAddress((void**)&q,   g_q);
    cudaGetSymbolAddress((void**)&k,   g_k);
    cudaGetSymbolAddress((void**)&qhp, g_qh);
    cudaGetSymbolAddress((void**)&khp, g_kh);
    cudaGetSymbolAddress((void**)&vtp, g_vt);
    cudaGetSymbolAddress((void**)&ao,  g_o);

    const int M = B_ * T_;  // 4096

    cudaFuncSetAttribute(qkv_gemm, cudaFuncAttributeMaxDynamicSharedMemorySize, GEMM_SMEM);
    cudaFuncSetAttribute(gemm_tf32, cudaFuncAttributeMaxDynamicSharedMemorySize, GEMM_SMEM);
    cudaFuncSetAttribute(flash_f16, cudaFuncAttributeMaxDynamicSharedMemorySize, FA_SMEM);

    // QKV projections; v written half+transposed
    qkv_gemm<<<768, 256, GEMM_SMEM>>>(x, Wq, Wk, Wv, q, k, vtp);

    // RMSNorm + RoPE -> half (q gets 1/sqrt(HD) folded in)
    rmsnorm_rope_h<<<(M * H_) / 8, 256>>>(q, qhp, q_scale, cosT, sinT, H_, M * H_,
                                          0.08838834764831845f);
    rmsnorm_rope_h<<<(M * KV_) / 8, 256>>>(k, khp, k_scale, cosT, sinT, KV_, M * KV_, 1.0f);

    // FP16 flash attention
    flash_f16<<<dim3(T_ / 128, B_ * H_), 256, FA_SMEM>>>(qhp, khp, vtp, ao);

    // Output projection
    gemm_tf32<<<dim3(D_ / 128, M / 128), 256, GEMM_SMEM>>>(ao, Wo, out, M, D_, H_ * HD_);
}

// round 15
// speedup vs baseline: 1.7272x; 1.3612x over previous
#include <cuda_runtime.h>
#include <cuda_fp16.h>
#include <math.h>

#define B_  2
#define T_  2048
#define D_  2048
#define H_  16
#define KV_ 4
#define HD_ 128

// Scratch (allocation-free rule: __device__ globals)
__device__ float  g_q [(size_t)B_ * T_ * H_  * HD_];   // fp32 q (pre-norm)
__device__ float  g_k [(size_t)B_ * T_ * KV_ * HD_];   // fp32 k (pre-norm)
__device__ __half g_qh[(size_t)B_ * T_ * H_  * HD_];   // half q (normed+rope+scaled)
__device__ __half g_kh[(size_t)B_ * T_ * KV_ * HD_];   // half k (normed+rope)
__device__ __half g_vt[(size_t)B_ * KV_ * HD_ * T_];   // half V transposed [b,g,hd,t]
__device__ float  g_o [(size_t)B_ * T_ * H_  * HD_];   // attention output

__device__ __forceinline__ void cp16(void* smem_ptr, const void* gptr) {
    unsigned s = (unsigned)__cvta_generic_to_shared(smem_ptr);
    asm volatile("cp.async.cg.shared.global [%0], [%1], 16;" :: "r"(s), "l"(gptr));
}

#define MMA_F16(cc, aa, bb)                                                    \
    asm volatile(                                                              \
        "mma.sync.aligned.m16n8k16.row.col.f32.f16.f16.f32 "                   \
        "{%0,%1,%2,%3}, {%4,%5,%6,%7}, {%8,%9}, {%0,%1,%2,%3};"                \
        : "+f"(cc[0]), "+f"(cc[1]), "+f"(cc[2]), "+f"(cc[3])                   \
        : "r"(aa[0]), "r"(aa[1]), "r"(aa[2]), "r"(aa[3]), "r"(bb[0]), "r"(bb[1]))

// ===========================================================================
// FP16 GEMM: C[M,N] = A[M,K] @ B[K,N], fp32 in (cvt to half at smem store),
// fp32 out. Block 128x128, K-tile 32, 8 warps (2Mx4N), m16n8k16, occ 2.
// A smem: half [128][40] (k-contig, pad 8). B smem: half2 [16][136]
// (k-pair interleaved, n-contig, pad 8). Both double-buffered.
// ===========================================================================
#define AH_STR  40    // halves per A row
#define BH2_STR 136   // half2 per B kk-row
#define A_BUF_H (128 * AH_STR)            // halves per A buffer
#define B_BUF_2 (16 * BH2_STR)            // half2 per B buffer
#define GEMM_SMEM_H (2 * (A_BUF_H * 2 + B_BUF_2 * 4))   // 37,888 B

struct GemmFrag { float c[4][4][4]; };

__device__ __forceinline__ void gemm_mainloop_h(
    const float* __restrict__ A, const float* __restrict__ B,
    __half* Ash, __half2* Bsh,
    int bm, int bn, int N, int K, GemmFrag& F)
{
    const int tid  = threadIdx.x;
    const int lane = tid & 31;
    const int warp = tid >> 5;
    const int la3  = lane & 3;
    const int r    = lane >> 2;
    const int wm = (warp >> 2) * 64;
    const int wn = (warp & 3) * 32;

    // A loader: rows ar+32i, cols ac..ac+3
    const int ar = tid >> 3;
    const int ac = (tid & 7) * 4;
    // B loader: k rows 2*bkk, 2*bkk+1, cols bn0..bn0+7
    const int bkk = tid >> 4;
    const int bn0 = (tid & 15) * 8;

    const float* Ag = A + (size_t)(bm + ar) * K + ac;
    const float* Bg = B + bn + bn0;

#pragma unroll
    for (int mt = 0; mt < 4; mt++)
#pragma unroll
        for (int nt = 0; nt < 4; nt++)
#pragma unroll
            for (int i = 0; i < 4; i++) F.c[mt][nt][i] = 0.f;

    float4 areg[4], b0[2], b1[2];
#pragma unroll
    for (int i = 0; i < 4; i++) areg[i] = *(const float4*)(Ag + (size_t)(i * 32) * K);
    b0[0] = *(const float4*)(Bg + (size_t)(2 * bkk) * N);
    b0[1] = *(const float4*)(Bg + (size_t)(2 * bkk) * N + 4);
    b1[0] = *(const float4*)(Bg + (size_t)(2 * bkk + 1) * N);
    b1[1] = *(const float4*)(Bg + (size_t)(2 * bkk + 1) * N + 4);

    // store tile 0 into buffer 0
#pragma unroll
    for (int i = 0; i < 4; i++) {
        __half2 h0 = __floats2half2_rn(areg[i].x, areg[i].y);
        __half2 h1 = __floats2half2_rn(areg[i].z, areg[i].w);
        uint2 u; u.x = *(unsigned*)&h0; u.y = *(unsigned*)&h1;
        *(uint2*)&Ash[(ar + i * 32) * AH_STR + ac] = u;
    }
    {
        const float* f0 = (const float*)b0;
        const float* f1 = (const float*)b1;
        uint4 u[2];
        unsigned* up = (unsigned*)u;
#pragma unroll
        for (int j = 0; j < 8; j++) {
            __half2 h = __floats2half2_rn(f0[j], f1[j]);
            up[j] = *(unsigned*)&h;
        }
        uint4* dst = (uint4*)&Bsh[bkk * BH2_STR + bn0];
        dst[0] = u[0]; dst[1] = u[1];
    }
    __syncthreads();

    int buf = 0;
    for (int k0 = 32; k0 <= K; k0 += 32) {
        const int nbuf = buf ^ 1;
        const bool more = (k0 < K);
        if (more) {
#pragma unroll
            for (int i = 0; i < 4; i++)
                areg[i] = *(const float4*)(Ag + (size_t)(i * 32) * K + k0);
            b0[0] = *(const float4*)(Bg + (size_t)(k0 + 2 * bkk) * N);
            b0[1] = *(const float4*)(Bg + (size_t)(k0 + 2 * bkk) * N + 4);
            b1[0] = *(const float4*)(Bg + (size_t)(k0 + 2 * bkk + 1) * N);
            b1[1] = *(const float4*)(Bg + (size_t)(k0 + 2 * bkk + 1) * N + 4);
        }

        const unsigned* Aw = (const unsigned*)(Ash + buf * A_BUF_H);
        const unsigned* Bw = (const unsigned*)(Bsh + buf * B_BUF_2);
#pragma unroll
        for (int ks = 0; ks < 2; ks++) {
            unsigned a[4][4], b[4][2];
#pragma unroll
            for (int mt = 0; mt < 4; mt++) {
                const unsigned* ap = Aw + (wm + mt * 16 + r) * (AH_STR / 2) + ks * 8 + la3;
                a[mt][0] = ap[0];
                a[mt][1] = ap[8 * (AH_STR / 2)];
                a[mt][2] = ap[4];
                a[mt][3] = ap[8 * (AH_STR / 2) + 4];
            }
#pragma unroll
            for (int nt = 0; nt < 4; nt++) {
                const unsigned* bp = Bw + (ks * 8 + la3) * BH2_STR + wn + nt * 8 + r;
                b[nt][0] = bp[0];
                b[nt][1] = bp[4 * BH2_STR];
            }
#pragma unroll
            for (int mt = 0; mt < 4; mt++)
#pragma unroll
                for (int nt = 0; nt < 4; nt++)
                    MMA_F16(F.c[mt][nt], a[mt], b[nt]);
        }

        if (more) {
            __half* An = Ash + nbuf * A_BUF_H;
            __half2* Bn = Bsh + nbuf * B_BUF_2;
#pragma unroll
            for (int i = 0; i < 4; i++) {
                __half2 h0 = __floats2half2_rn(areg[i].x, areg[i].y);
                __half2 h1 = __floats2half2_rn(areg[i].z, areg[i].w);
                uint2 u; u.x = *(unsigned*)&h0; u.y = *(unsigned*)&h1;
                *(uint2*)&An[(ar + i * 32) * AH_STR + ac] = u;
            }
            const float* f0 = (const float*)b0;
            const float* f1 = (const float*)b1;
            uint4 u[2];
            unsigned* up = (unsigned*)u;
#pragma unroll
            for (int j = 0; j < 8; j++) {
                __half2 h = __floats2half2_rn(f0[j], f1[j]);
                up[j] = *(unsigned*)&h;
            }
            uint4* dst = (uint4*)&Bn[bkk * BH2_STR + bn0];
            dst[0] = u[0]; dst[1] = u[1];
        }
        __syncthreads();
        buf = nbuf;
    }
}

__device__ __forceinline__ void gemm_store(float* __restrict__ C, int bm, int bn,
                                           int N, const GemmFrag& F) {
    const int lane = threadIdx.x & 31;
    const int warp = threadIdx.x >> 5;
    const int wm = (warp >> 2) * 64;
    const int wn = (warp & 3) * 32;
#pragma unroll
    for (int mt = 0; mt < 4; mt++)
#pragma unroll
        for (int nt = 0; nt < 4; nt++) {
            const int r0 = bm + wm + mt * 16 + (lane >> 2);
            const int cc = bn + wn + nt * 8 + (lane & 3) * 2;
            float2 v0 = {F.c[mt][nt][0], F.c[mt][nt][1]};
            float2 v1 = {F.c[mt][nt][2], F.c[mt][nt][3]};
            *(float2*)(C + (size_t)r0 * N + cc) = v0;
            *(float2*)(C + (size_t)(r0 + 8) * N + cc) = v1;
        }
}

// ===========================================================================
// Combined QKV projection GEMM (fp16 mma). q,k -> fp32 scratch; v -> half
// TRANSPOSED [b, g, hd, t]. grid.x = 768.
// ===========================================================================
__global__ __launch_bounds__(256, 2) void qkv_gemm(const float* __restrict__ x,
                                                   const float* __restrict__ Wq,
                                                   const float* __restrict__ Wk,
                                                   const float* __restrict__ Wv,
                                                   float* __restrict__ qo,
                                                   float* __restrict__ ko,
                                                   __half* __restrict__ vt) {
    extern __shared__ __half gsm_h[];
    __half* Ash = gsm_h;
    __half2* Bsh = (__half2*)(gsm_h + 2 * A_BUF_H);

    const int bx = blockIdx.x;
    int bm, bn, N, seg;
    const float* Bmat;
    float* Cmat = 0;
    if (bx < 512) {
        seg = 0; Bmat = Wq; Cmat = qo; N = H_ * HD_;
        bn = (bx & 15) * 128; bm = (bx >> 4) * 128;
    } else if (bx < 640) {
        const int l = bx - 512;
        seg = 1; Bmat = Wk; Cmat = ko; N = KV_ * HD_;
        bn = (l & 3) * 128; bm = (l >> 2) * 128;
    } else {
        const int l = bx - 640;
        seg = 2; Bmat = Wv; N = KV_ * HD_;
        bn = (l & 3) * 128; bm = (l >> 2) * 128;
    }

    GemmFrag F;
    gemm_mainloop_h(x, Bmat, Ash, Bsh, bm, bn, N, D_, F);

    if (seg != 2) {
        gemm_store(Cmat, bm, bn, N, F);
        return;
    }

    // v epilogue: half, transposed to [b, g, hd, t]
    const int lane = threadIdx.x & 31;
    const int warp = threadIdx.x >> 5;
    const int wm = (warp >> 2) * 64;
    const int wn = (warp & 3) * 32;
    const int r  = lane >> 2;
    const int la3 = lane & 3;
#pragma unroll
    for (int mt = 0; mt < 4; mt++) {
        const int r0 = bm + wm + mt * 16 + r;
        const int b0 = r0 >> 11;            // T_ = 2048
        const int t0 = r0 & (T_ - 1);
#pragma unroll
        for (int nt = 0; nt < 4; nt++) {
            const int col = bn + wn + nt * 8 + la3 * 2;
            const int g  = col >> 7;
            const int hd = col & 127;
            __half* dst = vt + ((size_t)(b0 * KV_ + g) * HD_ + hd) * T_;
            dst[t0]            = __float2half_rn(F.c[mt][nt][0]);
            dst[T_ + t0]       = __float2half_rn(F.c[mt][nt][1]);
            dst[t0 + 8]        = __float2half_rn(F.c[mt][nt][2]);
            dst[T_ + t0 + 8]   = __float2half_rn(F.c[mt][nt][3]);
        }
    }
}

// ===========================================================================
// Plain fp16 GEMM (O projection).
// ===========================================================================
__global__ __launch_bounds__(256, 2) void gemm_h(const float* __restrict__ A,
                                                 const float* __restrict__ B,
                                                 float* __restrict__ C,
                                                 int M, int N, int K) {
    extern __shared__ __half gsm_h[];
    __half* Ash = gsm_h;
    __half2* Bsh = (__half2*)(gsm_h + 2 * A_BUF_H);

    const int bm = blockIdx.y * 128;
    const int bn = blockIdx.x * 128;

    GemmFrag F;
    gemm_mainloop_h(A, B, Ash, Bsh, bm, bn, N, K, F);
    gemm_store(C, bm, bn, N, F);
}

// ---------------------------------------------------------------------------
// RMSNorm + RoPE; reads fp32, writes HALF (fold multiplies all outputs).
// ---------------------------------------------------------------------------
__global__ __launch_bounds__(256) void rmsnorm_rope_h(const float* __restrict__ in,
                                                      __half* __restrict__ outp,
                                                      const float* __restrict__ scale,
                                                      const float* __restrict__ cosT,
                                                      const float* __restrict__ sinT,
                                                      int nheads, int total_rows,
                                                      float fold) {
    const int warp = threadIdx.x >> 5;
    const int lane = threadIdx.x & 31;
    const int row = blockIdx.x * 8 + warp;
    if (row >= total_rows) return;
    const int t = (row / nheads) % T_;

    const float4* p = (const float4*)(in + (size_t)row * HD_);
    float4 x = p[lane];
    float ss = x.x * x.x + x.y * x.y + x.z * x.z + x.w * x.w;
#pragma unroll
    for (int o = 16; o > 0; o >>= 1) ss += __shfl_xor_sync(0xffffffffu, ss, o);
    const float rinv = rsqrtf(ss * (1.0f / HD_) + 1e-6f);

    const int d0 = lane * 4;
    float4 sc = *(const float4*)(scale + d0);
    float n0 = x.x * rinv * sc.x;
    float n1 = x.y * rinv * sc.y;
    float n2 = x.z * rinv * sc.z;
    float n3 = x.w * rinv * sc.w;

    const float c0 = cosT[(size_t)t * HD_ + d0];
    const float s0 = sinT[(size_t)t * HD_ + d0];
    const float c1 = cosT[(size_t)t * HD_ + d0 + 2];
    const float s1 = sinT[(size_t)t * HD_ + d0 + 2];

    const float o0 = (n0 * c0 - n1 * s0) * fold;
    const float o1 = (n1 * c0 + n0 * s0) * fold;
    const float o2 = (n2 * c1 - n3 * s1) * fold;
    const float o3 = (n3 * c1 + n2 * s1) * fold;

    __half2* q2 = (__half2*)(outp + (size_t)row * HD_ + d0);
    q2[0] = __floats2half2_rn(o0, o1);
    q2[1] = __floats2half2_rn(o2, o3);
}

// ---------------------------------------------------------------------------
// FP16 tensor-core causal GQA flash attention (unchanged from 201us version).
// ---------------------------------------------------------------------------
#define FQ_STR 136
#define FV_STR 40
#define FK_HALF (128 * FQ_STR)
#define FV_HALF (FK_HALF + 2 * 32 * FQ_STR)
#define FA_SMEM ((FV_HALF + 2 * 128 * FV_STR) * 2)

__global__ __launch_bounds__(256, 2) void flash_f16(const __half* __restrict__ qh,
                                                    const __half* __restrict__ kh,
                                                    const __half* __restrict__ vt,
                                                    float* __restrict__ o) {
    extern __shared__ __half hsm[];
    __half* Qs = hsm;
    __half* Ks = hsm + FK_HALF;
    __half* Vs = hsm + FV_HALF;
    const unsigned* Qw = (const unsigned*)Qs;
    const unsigned* Kw = (const unsigned*)Ks;
    const unsigned* Vw = (const unsigned*)Vs;

    const int tid  = threadIdx.x;
    const int warp = tid >> 5;
    const int lane = tid & 31;
    const int la3  = lane & 3;
    const int r    = lane >> 2;
    const int bh = blockIdx.y;
    const int b = bh >> 4;
    const int h = bh & 15;
    const int g = h >> 2;
    const int qb = (gridDim.x - 1) - blockIdx.x;   // heavy tiles first
    const int qbase = qb * 128;
    const int wm = warp * 16;
    const size_t bT = (size_t)b * T_;
    const __half* vbase = vt + (size_t)(b * KV_ + g) * HD_ * T_;

    const int ntiles = (qb + 1) * 4;

    for (int i = tid; i < 2048; i += 256) {
        const int row = i >> 4, ch = (i & 15) * 8;
        cp16(&Qs[row * FQ_STR + ch], qh + ((bT + qbase + row) * H_ + h) * HD_ + ch);
    }
    for (int i = tid; i < 512; i += 256) {
        const int row = i >> 4, ch = (i & 15) * 8;
        cp16(&Ks[row * FQ_STR + ch], kh + ((bT + row) * KV_ + g) * HD_ + ch);
    }
    for (int i = tid; i < 512; i += 256) {
        const int hd = i >> 2, ch = (i & 3) * 8;
        cp16(&Vs[hd * FV_STR + ch], vbase + (size_t)hd * T_ + ch);
    }
    asm volatile("cp.async.commit_group;" ::: "memory");

    float m0 = -1e30f, m1 = -1e30f, l0 = 0.f, l1 = 0.f;
    float acc[16][4];
#pragma unroll
    for (int ns = 0; ns < 16; ns++)
#pragma unroll
        for (int i = 0; i < 4; i++) acc[ns][i] = 0.f;

    const int row0 = qbase + wm + r;

    for (int j = 0; j < ntiles; j++) {
        const int kbase = j * 32;
        const int kbw = (j & 1) * 32 * (FQ_STR / 2);
        const int vbw = (j & 1) * 128 * (FV_STR / 2);

        asm volatile("cp.async.wait_group 0;" ::: "memory");
        __syncthreads();

        if (j + 1 < ntiles) {
            __half* Kn = Ks + ((j + 1) & 1) * 32 * FQ_STR;
            __half* Vn = Vs + ((j + 1) & 1) * 128 * FV_STR;
            const int nkb = kbase + 32;
            for (int i = tid; i < 512; i += 256) {
                const int row = i >> 4, ch = (i & 15) * 8;
                cp16(&Kn[row * FQ_STR + ch], kh + ((bT + nkb + row) * KV_ + g) * HD_ + ch);
            }
            for (int i = tid; i < 512; i += 256) {
                const int hd = i >> 2, ch = (i & 3) * 8;
                cp16(&Vn[hd * FV_STR + ch], vbase + (size_t)hd * T_ + nkb + ch);
            }
            asm volatile("cp.async.commit_group;" ::: "memory");
        }

        const bool active = (kbase <= qbase + wm + 15);
        if (active) {
            float s[4][4];
#pragma unroll
            for (int ns = 0; ns < 4; ns++)
#pragma unroll
                for (int i = 0; i < 4; i++) s[ns][i] = 0.f;

#pragma unroll
            for (int kc = 0; kc < 8; kc++) {
                unsigned a[4];
                const unsigned* ap = Qw + (wm + r) * (FQ_STR / 2) + kc * 8 + la3;
                a[0] = ap[0];
                a[1] = ap[8 * (FQ_STR / 2)];
                a[2] = ap[4];
                a[3] = ap[8 * (FQ_STR / 2) + 4];
#pragma unroll
                for (int ns = 0; ns < 4; ns++) {
                    const unsigned* bp = Kw + kbw + (ns * 8 + r) * (FQ_STR / 2) + kc * 8 + la3;
                    unsigned bf[2];
                    bf[0] = bp[0];
                    bf[1] = bp[4];
                    MMA_F16(s[ns], a, bf);
                }
            }

            if (kbase + 31 > qbase + wm) {
#pragma unroll
                for (int ns = 0; ns < 4; ns++) {
                    const int col = kbase + ns * 8 + la3 * 2;
                    if (col > row0)     s[ns][0] = -1e30f;
                    if (col + 1 > row0) s[ns][1] = -1e30f;
                    if (col > row0 + 8)     s[ns][2] = -1e30f;
                    if (col + 1 > row0 + 8) s[ns][3] = -1e30f;
                }
            }

            float mx0 = -1e30f, mx1 = -1e30f;
#pragma unroll
            for (int ns = 0; ns < 4; ns++) {
                mx0 = fmaxf(mx0, fmaxf(s[ns][0], s[ns][1]));
                mx1 = fmaxf(mx1, fmaxf(s[ns][2], s[ns][3]));
            }
            mx0 = fmaxf(mx0, __shfl_xor_sync(0xffffffffu, mx0, 1));
            mx0 = fmaxf(mx0, __shfl_xor_sync(0xffffffffu, mx0, 2));
            mx1 = fmaxf(mx1, __shfl_xor_sync(0xffffffffu, mx1, 1));
            mx1 = fmaxf(mx1, __shfl_xor_sync(0xffffffffu, mx1, 2));

            const float mn0 = fmaxf(m0, mx0);
            const float mn1 = fmaxf(m1, mx1);
            const float al0 = __expf(m0 - mn0);
            const float al1 = __expf(m1 - mn1);
            m0 = mn0; m1 = mn1;

            float p[4][4];
            float sum0 = 0.f, sum1 = 0.f;
#pragma unroll
            for (int ns = 0; ns < 4; ns++) {
                p[ns][0] = __expf(s[ns][0] - mn0);
                p[ns][1] = __expf(s[ns][1] - mn0);
                p[ns][2] = __expf(s[ns][2] - mn1);
                p[ns][3] = __expf(s[ns][3] - mn1);
                sum0 += p[ns][0] + p[ns][1];
                sum1 += p[ns][2] + p[ns][3];
            }
            sum0 += __shfl_xor_sync(0xffffffffu, sum0, 1);
            sum0 += __shfl_xor_sync(0xffffffffu, sum0, 2);
            sum1 += __shfl_xor_sync(0xffffffffu, sum1, 1);
            sum1 += __shfl_xor_sync(0xffffffffu, sum1, 2);
            l0 = l0 * al0 + sum0;
            l1 = l1 * al1 + sum1;

#pragma unroll
            for (int ns = 0; ns < 16; ns++) {
                acc[ns][0] *= al0; acc[ns][1] *= al0;
                acc[ns][2] *= al1; acc[ns][3] *= al1;
            }

#pragma unroll
            for (int kc = 0; kc < 2; kc++) {
                unsigned a[4];
                __half2 h0 = __floats2half2_rn(p[2 * kc][0],     p[2 * kc][1]);
                __half2 h1 = __floats2half2_rn(p[2 * kc][2],     p[2 * kc][3]);
                __half2 h2 = __floats2half2_rn(p[2 * kc + 1][0], p[2 * kc + 1][1]);
                __half2 h3 = __floats2half2_rn(p[2 * kc + 1][2], p[2 * kc + 1][3]);
                a[0] = *(unsigned*)&h0;
                a[1] = *(unsigned*)&h1;
                a[2] = *(unsigned*)&h2;
                a[3] = *(unsigned*)&h3;
#pragma unroll
                for (int ns = 0; ns < 16; ns++) {
                    const unsigned* bp = Vw + vbw + (ns * 8 + r) * (FV_STR / 2) + kc * 8 + la3;
                    unsigned bf[2];
                    bf[0] = bp[0];
                    bf[1] = bp[4];
                    MMA_F16(acc[ns], a, bf);
                }
            }
        }
    }

    const float inv0 = 1.0f / l0;
    const float inv1 = 1.0f / l1;
    float* o0 = o + ((bT + row0) * H_ + h) * HD_;
    float* o1 = o + ((bT + row0 + 8) * H_ + h) * HD_;
#pragma unroll
    for (int ns = 0; ns < 16; ns++) {
        const int col = ns * 8 + la3 * 2;
        float2 v0 = {acc[ns][0] * inv0, acc[ns][1] * inv0};
        float2 v1 = {acc[ns][2] * inv1, acc[ns][3] * inv1};
        *(float2*)(o0 + col) = v0;
        *(float2*)(o1 + col) = v1;
    }
}

// ---------------------------------------------------------------------------
extern "C" void kernel_launch(void* const* d_in, const int* in_sizes, int n_in,
                              void* d_out, int out_size) {
    const float* x       = (const float*)d_in[0];
    const float* Wq      = (const float*)d_in[1];
    const float* Wk      = (const float*)d_in[2];
    const float* Wv      = (const float*)d_in[3];
    const float* Wo      = (const float*)d_in[4];
    const float* q_scale = (const float*)d_in[5];
    const float* k_scale = (const float*)d_in[6];
    const float* cosT    = (const float*)d_in[7];
    const float* sinT    = (const float*)d_in[8];
    float* out = (float*)d_out;

    float *q, *k, *ao;
    __half *qhp, *khp, *vtp;
    cudaGetSymbolAddress((void**)&q,   g_q);
    cudaGetSymbolAddress((void**)&k,   g_k);
    cudaGetSymbolAddress((void**)&qhp, g_qh);
    cudaGetSymbolAddress((void**)&khp, g_kh);
    cudaGetSymbolAddress((void**)&vtp, g_vt);
    cudaGetSymbolAddress((void**)&ao,  g_o);

    const int M = B_ * T_;  // 4096

    cudaFuncSetAttribute(qkv_gemm, cudaFuncAttributeMaxDynamicSharedMemorySize, GEMM_SMEM_H);
    cudaFuncSetAttribute(gemm_h, cudaFuncAttributeMaxDynamicSharedMemorySize, GEMM_SMEM_H);
    cudaFuncSetAttribute(flash_f16, cudaFuncAttributeMaxDynamicSharedMemorySize, FA_SMEM);

    // QKV projections (fp16 mma); v written half+transposed
    qkv_gemm<<<768, 256, GEMM_SMEM_H>>>(x, Wq, Wk, Wv, q, k, vtp);

    // RMSNorm + RoPE -> half (q gets 1/sqrt(HD) folded in)
    rmsnorm_rope_h<<<(M * H_) / 8, 256>>>(q, qhp, q_scale, cosT, sinT, H_, M * H_,
                                          0.08838834764831845f);
    rmsnorm_rope_h<<<(M * KV_) / 8, 256>>>(k, khp, k_scale, cosT, sinT, KV_, M * KV_, 1.0f);

    // FP16 flash attention
    flash_f16<<<dim3(T_ / 128, B_ * H_), 256, FA_SMEM>>>(qhp, khp, vtp, ao);

    // Output projection (fp16 mma)
    gemm_h<<<dim3(D_ / 128, M / 128), 256, GEMM_SMEM_H>>>(ao, Wo, out, M, D_, H_ * HD_);
}